// round 17
// baseline (speedup 1.0000x reference)
#include <cuda_runtime.h>

// SuperLoss mean, single-kernel. loss_i = (l-tau)*sigma + 0.25*ln(sigma)^2,
// sigma = exp(-W0(y)), y = max(-1/e, 2*(l-tau)).
//
// w = -1 + p*g(p), p = sqrt(max(2e*t2 + 2, 0)), t2 = 2*(l-tau).
// Deg-5 poly for g pre-scaled by -log2e: z = -w*log2e feeds ex2.approx;
// 0.25*w^2 = K*z^2 in the final combine. Per-element arithmetic bit-identical
// to R9-R15 (rel_err 2.665978e-7).
//
// R16: ALL-SCALAR math. Counter closure on R15 showed ~13-16 of 35 issued
// inst/pair-slot were pack/unpack movs at the scalar<->f32x2 boundaries;
// FFMA2 halved fma-pipe busy (to 40%, idle headroom) while inflating issue.
// Scalar drops to 13 inst/elem, no movs; fma pipe becomes the binding
// resource (~39k cyc floor). R15's block-contiguous tile + double-buffered
// immediate-offset LDG.128 pipeline retained unchanged.

#define NEG_2TAU  (-11.5981853089210513f)
#define TWO_E     ( 5.43656365691809047f)
#define LOG2E_F   ( 1.44269504088896341f)

#define D5 ( 4.8619e-4f)
#define D4 (-7.70688e-3f)
#define D3 ( 4.942817e-2f)
#define D2 (-1.7750919e-1f)
#define D1 ( 4.7082352e-1f)
#define D0 (-1.44269504f)

#define NBLOCKS  1024
#define NTHREADS 256
#define GPT      32                 // float4 groups per thread
#define GPB      (NTHREADS * GPT)   // 8192 groups per block (128KiB)

__device__ float g_partA[NBLOCKS];
__device__ float g_partB[NBLOCKS];
__device__ unsigned int g_cnt = 0;   // self-resets via atomicInc wraparound

__device__ __forceinline__ float fsqrt(float x) {
    float r; asm("sqrt.approx.f32 %0, %1;" : "=f"(r) : "f"(x)); return r;
}
__device__ __forceinline__ float fex2(float x) {
    float r; asm("ex2.approx.f32 %0, %1;" : "=f"(r) : "f"(x)); return r;
}

// Scalar element: 10 FFMA + 1 FMNMX + 2 MUFU. Bit-identical to the packed
// version's per-lane arithmetic (fma.rn.f32x2 == 2x fma.rn).
__device__ __forceinline__ void loss_elem(float l, float& accA, float& accB) {
    float t2 = fmaf(2.0f, l, NEG_2TAU);            // 2*l - 2tau
    float s  = fmaxf(fmaf(TWO_E, t2, 2.0f), 0.0f); // clamp on s (R9 path)
    float p  = fsqrt(s);
    float h  = fmaf(p, D5, D4);
    h = fmaf(p, h, D3);
    h = fmaf(p, h, D2);
    h = fmaf(p, h, D1);
    h = fmaf(p, h, D0);
    float z = fmaf(p, h, LOG2E_F);                 // z = -w*log2e
    accB = fmaf(z, z, accB);
    float sg = fex2(z);                            // sigma = exp(-w)
    accA = fmaf(t2, sg, accA);
}

__device__ __forceinline__ void do_v4(float4 v, float& a0, float& a1,
                                      float& a2, float& a3,
                                      float& b0, float& b1,
                                      float& b2, float& b3) {
    loss_elem(v.x, a0, b0);
    loss_elem(v.y, a1, b1);
    loss_elem(v.z, a2, b2);
    loss_elem(v.w, a3, b3);
}

__global__ void __launch_bounds__(NTHREADS, 4)
sl_kernel(const float* __restrict__ in, long long n, float* __restrict__ out) {
    float a0 = 0.f, a1 = 0.f, a2 = 0.f, a3 = 0.f;
    float b0 = 0.f, b1 = 0.f, b2 = 0.f, b3 = 0.f;

    const float4* __restrict__ in4 = (const float4*)in;
    int n4 = (int)(n >> 2);                      // float4 groups

    if (n4 == NBLOCKS * GPB) {
        // Contiguous 128KiB block tile. Batch k (k=0..7), thread t:
        // groups {t + j*256 + k*1024, j=0..3} — coalesced, immediate offsets.
        const float4* base = in4 + (size_t)blockIdx.x * GPB + threadIdx.x;

#define LD(Bf, k)                                      \
        do {                                           \
            Bf##0 = __ldcs(base + (k) * 1024 + 0);     \
            Bf##1 = __ldcs(base + (k) * 1024 + 256);   \
            Bf##2 = __ldcs(base + (k) * 1024 + 512);   \
            Bf##3 = __ldcs(base + (k) * 1024 + 768);   \
        } while (0)
#define CP(Bf)                                                  \
        do {                                                    \
            do_v4(Bf##0, a0, a1, a2, a3, b0, b1, b2, b3);       \
            do_v4(Bf##1, a0, a1, a2, a3, b0, b1, b2, b3);       \
            do_v4(Bf##2, a0, a1, a2, a3, b0, b1, b2, b3);       \
            do_v4(Bf##3, a0, a1, a2, a3, b0, b1, b2, b3);       \
        } while (0)

        float4 A0, A1, A2, A3, B0, B1, B2, B3;
        LD(A, 0);
        LD(B, 1);
        CP(A); LD(A, 2);
        CP(B); LD(B, 3);
        CP(A); LD(A, 4);
        CP(B); LD(B, 5);
        CP(A); LD(A, 6);
        CP(B); LD(B, 7);
        CP(A);
        CP(B);
#undef LD
#undef CP
    } else {
        // Generic fallback: grid-stride.
        int tid    = blockIdx.x * NTHREADS + threadIdx.x;
        int stride = NBLOCKS * NTHREADS;
        for (int i = tid; i < n4; i += stride) {
            float4 v = __ldcs(&in4[i]);
            do_v4(v, a0, a1, a2, a3, b0, b1, b2, b3);
        }
    }

    float a = (a0 + a1) + (a2 + a3);
    float b = (b0 + b1) + (b2 + b3);

#pragma unroll
    for (int o = 16; o > 0; o >>= 1) {
        a += __shfl_xor_sync(0xffffffffu, a, o);
        b += __shfl_xor_sync(0xffffffffu, b, o);
    }

    __shared__ float wsA[8], wsB[8];
    int lane = threadIdx.x & 31;
    int wid  = threadIdx.x >> 5;
    if (lane == 0) { wsA[wid] = a; wsB[wid] = b; }
    __syncthreads();

    __shared__ bool isLast;
    if (threadIdx.x == 0) {
        float ba = 0.f, bb = 0.f;
#pragma unroll
        for (int k = 0; k < 8; ++k) { ba += wsA[k]; bb += wsB[k]; }
        __stcg(&g_partA[blockIdx.x], ba);
        __stcg(&g_partB[blockIdx.x], bb);
        __threadfence();
        unsigned int old = atomicInc(&g_cnt, gridDim.x - 1);  // wraps to 0 on last
        isLast = (old == gridDim.x - 1);
    }
    __syncthreads();

    if (isLast) {
        double da = 0.0, db = 0.0;
        for (int k = threadIdx.x; k < NBLOCKS; k += NTHREADS) {
            da += (double)__ldcg(&g_partA[k]);
            db += (double)__ldcg(&g_partB[k]);
        }
#pragma unroll
        for (int o = 16; o > 0; o >>= 1) {
            da += __shfl_xor_sync(0xffffffffu, da, o);
            db += __shfl_xor_sync(0xffffffffu, db, o);
        }
        __shared__ double dsA[8], dsB[8];
        if (lane == 0) { dsA[wid] = da; dsB[wid] = db; }
        __syncthreads();
        if (threadIdx.x == 0) {
            double ta = 0.0, tb = 0.0;
#pragma unroll
            for (int k = 0; k < 8; ++k) { ta += dsA[k]; tb += dsB[k]; }
            const double K = 0.12011325347955035;  // 0.25*ln(2)^2
            out[0] = (float)((0.5 * ta + K * tb) / (double)n);
        }
    }
}

extern "C" void kernel_launch(void* const* d_in, const int* in_sizes, int n_in,
                              void* d_out, int out_size) {
    const float* l_i = (const float*)d_in[0];
    long long n = (long long)in_sizes[0];
    float* out = (float*)d_out;
    sl_kernel<<<NBLOCKS, NTHREADS>>>(l_i, n, out);
}